// round 8
// baseline (speedup 1.0000x reference)
#include <cuda_runtime.h>
#include <cuda_fp16.h>
#include <cstdint>
#include <cstddef>

#define NT 512
#define NH 128
#define ND 32
#define CS 8
#define NTHR 512
#define NB 64
#define BSTR 68
#define DSTR 34

__device__ float g_deriv[(size_t)NT * 3 * NB * ND];

__global__ void prep_deriv(const float* __restrict__ ts, const float* __restrict__ cd,
                           const float* __restrict__ cc, const float* __restrict__ cb) {
    int b = blockIdx.x, chunk = blockIdx.y;
    int sl = threadIdx.x >> 5, d = threadIdx.x & 31;
    int s = chunk * 16 + sl;
    __shared__ float tsv[NT];
    for (int i = threadIdx.x; i < NT; i += 512) tsv[i] = ts[(size_t)b * NT + i];
    __syncthreads();
    float dt = tsv[1] - tsv[0], t0 = tsv[0];
    for (int i = 0; i < s; ++i) t0 += dt;          // exact fp32 carry, matches scan
    for (int stg = 0; stg < 3; ++stg) {
        float te = (stg == 0) ? t0 : ((stg == 1) ? t0 + 0.5f * dt : t0 + 0.75f * dt);
        int idx = 0;
        #pragma unroll
        for (int stp = 256; stp > 0; stp >>= 1) {
            int c2 = idx + stp;
            if (c2 < NT && tsv[c2] <= te) idx = c2;
        }
        if (idx > NT - 2) idx = NT - 2;
        float fr = te - tsv[idx];
        size_t off = ((size_t)b * (NT - 1) + idx) * ND + d;
        g_deriv[(((size_t)s * 3 + stg) * NB + b) * ND + d] =
            cb[off] + fr * (2.0f * cc[off] + fr * 3.0f * cd[off]);
    }
}

struct __align__(16) SM {
    uint32_t W0q[4 * NH * 20];
    uint32_t W1q[4 * NH * 20];
    uint32_t Bt[CS * BSTR];
    float    drv[2][3][CS * DSTR];
    float    y[NH], ytmp[NH], h1[NH];
    float    kst[3][NH];
    uint32_t h2stage[64];          // outgoing h2, 256 B
    float    kstage[CS][16];       // outgoing k slices, 64 B per dest batch
    float    b0v[NH], b1v[NH], lwv[NH];
    float    red[4];
    float    a0s[ND];
    unsigned long long bbar, kbar;
};

__device__ __forceinline__ uint32_t smem_u32(const void* p) {
    uint32_t a;
    asm("{ .reg .u64 t; cvta.to.shared.u64 t, %1; cvt.u32.u64 %0, t; }" : "=r"(a) : "l"(p));
    return a;
}
__device__ __forceinline__ uint32_t mapa_u32(uint32_t addr, uint32_t rank) {
    uint32_t r;
    asm("mapa.shared::cluster.u32 %0, %1, %2;" : "=r"(r) : "r"(addr), "r"(rank));
    return r;
}
__device__ __forceinline__ void bulk_s2s(uint32_t dst, uint32_t src, uint32_t bytes, uint32_t mb) {
    asm volatile("cp.async.bulk.shared::cluster.shared::cta.mbarrier::complete_tx::bytes "
                 "[%0], [%1], %2, [%3];" :: "r"(dst), "r"(src), "r"(bytes), "r"(mb) : "memory");
}
__device__ __forceinline__ void fence_pa() {
    asm volatile("fence.proxy.async.shared::cta;" ::: "memory");
}
__device__ __forceinline__ void mbar_init(uint32_t mb, uint32_t cnt) {
    asm volatile("mbarrier.init.shared.b64 [%0], %1;" :: "r"(mb), "r"(cnt) : "memory");
}
__device__ __forceinline__ void mbar_expect(uint32_t mb, uint32_t tx) {
    asm volatile("mbarrier.arrive.expect_tx.shared::cta.b64 _, [%0], %1;"
                 :: "r"(mb), "r"(tx) : "memory");
}
__device__ __forceinline__ void mbar_wait(uint32_t mb, uint32_t parity) {
    uint32_t done;
    asm volatile("{\n\t.reg .pred p;\n\t"
                 "mbarrier.try_wait.parity.acquire.cluster.shared::cta.b64 p, [%1], %2;\n\t"
                 "selp.b32 %0, 1, 0, p;\n\t}" : "=r"(done) : "r"(mb), "r"(parity) : "memory");
    if (!done) {
        asm volatile("{\n\t.reg .pred P1;\n\t"
                     "WL_%=:\n\t"
                     "mbarrier.try_wait.parity.acquire.cluster.shared::cta.b64 P1, [%0], %1, 0x989680;\n\t"
                     "@P1 bra.uni WD_%=;\n\t"
                     "bra.uni WL_%=;\n\t"
                     "WD_%=:\n\t}" :: "r"(mb), "r"(parity) : "memory");
    }
}
#define CLUSTER_SYNC() do { \
    asm volatile("barrier.cluster.arrive.aligned;" ::: "memory"); \
    asm volatile("barrier.cluster.wait.aligned;"   ::: "memory"); } while (0)

__device__ __forceinline__ void mma16816(float* c, const uint32_t* a, uint32_t b0, uint32_t b1) {
    asm volatile("mma.sync.aligned.m16n8k16.row.col.f32.f16.f16.f32 "
                 "{%0,%1,%2,%3}, {%4,%5,%6,%7}, {%8,%9}, {%0,%1,%2,%3};"
                 : "+f"(c[0]), "+f"(c[1]), "+f"(c[2]), "+f"(c[3])
                 : "r"(a[0]), "r"(a[1]), "r"(a[2]), "r"(a[3]), "r"(b0), "r"(b1));
}
__device__ __forceinline__ float tanh_fast(float x) {
    float y; asm("tanh.approx.f32 %0, %1;" : "=f"(y) : "f"(x)); return y;
}
__device__ __forceinline__ float softplus_f(float x) {
    return fmaxf(x, 0.0f) + log1pf(expf(-fabsf(x)));
}
__device__ __forceinline__ uint32_t pack_h2(float a, float b) {
    __half2 h = __floats2half2_rn(a, b);
    return *reinterpret_cast<uint32_t*>(&h);
}
__device__ __forceinline__ float2 h2f(uint32_t u) {
    __half2 h = *reinterpret_cast<__half2*>(&u);
    return __half22float2(h);
}

__global__ void __launch_bounds__(NTHR, 1) __cluster_dims__(CS, 1, 1)
cde_kernel(const float* __restrict__ ts, const float* __restrict__ ca,
           const float* __restrict__ iW0, const float* __restrict__ ib0,
           const float* __restrict__ iW1, const float* __restrict__ ib1,
           const float* __restrict__ iW2, const float* __restrict__ ib2,
           const float* __restrict__ fW0, const float* __restrict__ fb0,
           const float* __restrict__ fW1, const float* __restrict__ fb1,
           const float* __restrict__ fW2, const float* __restrict__ fb2,
           const float* __restrict__ lW, const float* __restrict__ lb,
           float* __restrict__ out)
{
    extern __shared__ char smraw[];
    SM* S = reinterpret_cast<SM*>(smraw);
    const int tid = threadIdx.x, wid = tid >> 5, lane = tid & 31;
    const int gid = lane >> 2, tig = lane & 3;
    const int batch = blockIdx.x;
    const int rank = batch & (CS - 1), cbat0 = batch & ~(CS - 1);

    const uint32_t bt_a   = smem_u32(&S->Bt[0]);
    const uint32_t kst_a  = smem_u32(&S->kst[0][0]);
    const uint32_t bbar_a = smem_u32(&S->bbar);
    const uint32_t kbar_a = smem_u32(&S->kbar);
    const uint32_t h2st_a = smem_u32(&S->h2stage[0]);
    const uint32_t kstg_a = smem_u32(&S->kstage[0][0]);

    if (tid == 0) {
        mbar_init(bbar_a, 1);
        mbar_init(kbar_a, 1);
        mbar_expect(bbar_a, 2048);
        mbar_expect(kbar_a, 512);
        asm volatile("fence.mbarrier_init.release.cluster;" ::: "memory");
    }

    for (int i = tid; i < NH * 64; i += NTHR) {
        int row = i >> 6, w = i & 63;
        int kq = w >> 4, ii = w & 15;
        S->W0q[(kq * NH + row) * 20 + ii] = pack_h2(fW0[row * NH + 2 * w], fW0[row * NH + 2 * w + 1]);
        S->W1q[(kq * NH + row) * 20 + ii] = pack_h2(fW1[row * NH + 2 * w], fW1[row * NH + 2 * w + 1]);
    }
    if (tid < NH) { S->b0v[tid] = fb0[tid]; S->b1v[tid] = fb1[tid]; S->lwv[tid] = lW[tid]; }

    const int rowbase = rank * 512 + wid * 32;
    uint32_t areg[2][8][4];
    float b2v[2][2];
    #pragma unroll
    for (int t = 0; t < 2; ++t) {
        int r0g = rowbase + t * 16 + gid, r1g = r0g + 8;
        b2v[t][0] = fb2[r0g]; b2v[t][1] = fb2[r1g];
        #pragma unroll
        for (int ks = 0; ks < 8; ++ks) {
            int c0 = ks * 16 + 2 * tig;
            const float* w0 = fW2 + (size_t)r0g * NH;
            const float* w1 = fW2 + (size_t)r1g * NH;
            areg[t][ks][0] = pack_h2(w0[c0], w0[c0 + 1]);
            areg[t][ks][1] = pack_h2(w1[c0], w1[c0 + 1]);
            areg[t][ks][2] = pack_h2(w0[c0 + 8], w0[c0 + 9]);
            areg[t][ks][3] = pack_h2(w1[c0 + 8], w1[c0 + 9]);
        }
    }
    __syncthreads();

    if (tid < ND) S->a0s[tid] = ca[(size_t)batch * (NT - 1) * ND + tid];
    __syncthreads();
    if (tid < NH) {
        float a = ib0[tid];
        #pragma unroll
        for (int k = 0; k < ND; ++k) a = fmaf(iW0[tid * ND + k], S->a0s[k], a);
        S->h1[tid] = fmaxf(a, 0.0f);
    }
    __syncthreads();
    if (tid < NH) {
        float a = ib1[tid];
        for (int k = 0; k < NH; ++k) a = fmaf(iW1[tid * NH + k], S->h1[k], a);
        S->ytmp[tid] = fmaxf(a, 0.0f);
    }
    __syncthreads();
    if (tid < NH) {
        float a = ib2[tid];
        for (int k = 0; k < NH; ++k) a = fmaf(iW2[tid * NH + k], S->ytmp[k], a);
        S->y[tid] = a;
    }

    if (tid < 192) {
        int stgp = tid >> 6, r = tid & 63, b = r >> 3, seg = r & 7;
        float4 v = *(const float4*)&g_deriv[(((size_t)0 * 3 + stgp) * NB + cbat0 + b) * ND + seg * 4];
        float* dp = &S->drv[0][stgp][b * DSTR + seg * 4];
        *(float2*)dp = make_float2(v.x, v.y);
        *(float2*)(dp + 2) = make_float2(v.z, v.w);
    }
    __syncthreads();
    CLUSTER_SYNC();

    const float dtv = ts[(size_t)batch * NT + 1] - ts[(size_t)batch * NT];
    const float lbv = lb[0];
    uint32_t bpar = 0, kpar = 0;

    const int lrow = wid * 8 + (lane & 7);
    const int kq = lane >> 3;
    const uint32_t* w0base = S->W0q + (kq * NH + lrow) * 20;
    const uint32_t* w1base = S->W1q + (kq * NH + lrow) * 20;

    // bulk-sender addresses (warp 0, lanes 0..7; peer = lane)
    const uint32_t dstB = (wid == 0 && lane < 8) ? mapa_u32(bt_a + (uint32_t)(rank * BSTR * 4), (uint32_t)lane) : 0;
    const uint32_t mbB  = (wid == 0 && lane < 8) ? mapa_u32(bbar_a, (uint32_t)lane) : 0;
    const uint32_t dstK = (wid == 0 && lane < 8) ? mapa_u32(kst_a + (uint32_t)(rank * 64), (uint32_t)lane) : 0;
    const uint32_t mbK  = (wid == 0 && lane < 8) ? mapa_u32(kbar_a, (uint32_t)lane) : 0;
    const uint32_t srcK = kstg_a + (uint32_t)(lane * 64);

    for (int s = 0; s < NT; ++s) {
        const float* dbuf0 = S->drv[s & 1][0];
        #pragma unroll 1
        for (int stg = 0; stg < 3; ++stg) {
            __syncthreads();
            const float* yin = (stg == 0) ? S->y : S->ytmp;

            float4 pf;
            if (stg == 0) {
                if (tid == 0 && s > 0) {
                    float v = S->red[0] + S->red[1] + S->red[2] + S->red[3] + lbv;
                    out[(size_t)batch * NT + s - 1] = 1.0f / (1.0f + expf(-v));
                }
                if (tid < 192) {
                    int s1 = (s + 1 < NT) ? s + 1 : NT - 1;
                    int stgp = tid >> 6, r = tid & 63, b = r >> 3, seg = r & 7;
                    pf = *(const float4*)&g_deriv[(((size_t)s1 * 3 + stgp) * NB + cbat0 + b) * ND + seg * 4];
                }
            }
            {   // layer 1, 4 accumulators
                float a0 = 0.f, a1 = 0.f, a2 = 0.f, a3 = 0.f;
                #pragma unroll
                for (int i = 0; i < 4; ++i) {
                    uint4 w = *(const uint4*)(w0base + i * 4);
                    float4 ya = *(const float4*)&yin[kq * 32 + i * 8];
                    float4 yb = *(const float4*)&yin[kq * 32 + i * 8 + 4];
                    float2 f0 = h2f(w.x), f1 = h2f(w.y), f2 = h2f(w.z), f3 = h2f(w.w);
                    a0 = fmaf(f0.x, ya.x, fmaf(f0.y, ya.y, a0));
                    a1 = fmaf(f1.x, ya.z, fmaf(f1.y, ya.w, a1));
                    a2 = fmaf(f2.x, yb.x, fmaf(f2.y, yb.y, a2));
                    a3 = fmaf(f3.x, yb.z, fmaf(f3.y, yb.w, a3));
                }
                float acc = (a0 + a1) + (a2 + a3);
                acc += __shfl_xor_sync(0xffffffffu, acc, 8);
                acc += __shfl_xor_sync(0xffffffffu, acc, 16);
                if (lane < 8) S->h1[lrow] = softplus_f(acc + S->b0v[lrow]);
            }
            if (stg == 0 && tid < 192) {
                int stgp = tid >> 6, r = tid & 63, b = r >> 3, seg = r & 7;
                float* dp = &S->drv[(s + 1) & 1][stgp][b * DSTR + seg * 4];
                *(float2*)dp = make_float2(pf.x, pf.y);
                *(float2*)(dp + 2) = make_float2(pf.z, pf.w);
            }
            __syncthreads();

            float val;
            {   // layer 2, 4 accumulators
                float a0 = 0.f, a1 = 0.f, a2 = 0.f, a3 = 0.f;
                #pragma unroll
                for (int i = 0; i < 4; ++i) {
                    uint4 w = *(const uint4*)(w1base + i * 4);
                    float4 ya = *(const float4*)&S->h1[kq * 32 + i * 8];
                    float4 yb = *(const float4*)&S->h1[kq * 32 + i * 8 + 4];
                    float2 f0 = h2f(w.x), f1 = h2f(w.y), f2 = h2f(w.z), f3 = h2f(w.w);
                    a0 = fmaf(f0.x, ya.x, fmaf(f0.y, ya.y, a0));
                    a1 = fmaf(f1.x, ya.z, fmaf(f1.y, ya.w, a1));
                    a2 = fmaf(f2.x, yb.x, fmaf(f2.y, yb.y, a2));
                    a3 = fmaf(f3.x, yb.z, fmaf(f3.y, yb.w, a3));
                }
                float acc = (a0 + a1) + (a2 + a3);
                acc += __shfl_xor_sync(0xffffffffu, acc, 8);
                acc += __shfl_xor_sync(0xffffffffu, acc, 16);
                val = softplus_f(acc + S->b1v[lrow]);
            }
            // stage h2 (fp16) locally, then 8 bulk sends
            {
                float lo = __shfl_sync(0xffffffffu, val, 2 * (lane & 3));
                float hi = __shfl_sync(0xffffffffu, val, 2 * (lane & 3) + 1);
                if (lane < 4) S->h2stage[wid * 4 + lane] = pack_h2(lo, hi);
            }
            __syncthreads();
            if (wid == 0 && lane < 8) {
                fence_pa();
                bulk_s2s(dstB, h2st_a, 256, mbB);
            }
            mbar_wait(bbar_a, bpar); bpar ^= 1;
            if (tid == 0) mbar_expect(bbar_a, 2048);

            {   // HMMA + epilogue
                float c0[4] = {0.f, 0.f, 0.f, 0.f};
                float c1[4] = {0.f, 0.f, 0.f, 0.f};
                const uint32_t* BtW = S->Bt;
                #pragma unroll
                for (int ks = 0; ks < 8; ++ks) {
                    uint32_t b0 = BtW[gid * BSTR + ks * 8 + tig];
                    uint32_t b1 = BtW[gid * BSTR + ks * 8 + tig + 4];
                    mma16816(c0, areg[0][ks], b0, b1);
                    mma16816(c1, areg[1][ks], b0, b1);
                }
                const float* dvE = dbuf0 + (size_t)stg * (CS * DSTR) + (2 * tig) * DSTR;
                const float* dvO = dvE + DSTR;
                float pe, po;
                {
                    float z00 = tanh_fast(c0[0] + b2v[0][0]);
                    float z02 = tanh_fast(c0[2] + b2v[0][1]);
                    float z10 = tanh_fast(c1[0] + b2v[1][0]);
                    float z12 = tanh_fast(c1[2] + b2v[1][1]);
                    pe = z00 * dvE[gid] + z02 * dvE[gid + 8] + z10 * dvE[gid + 16] + z12 * dvE[gid + 24];
                    float z01 = tanh_fast(c0[1] + b2v[0][0]);
                    float z03 = tanh_fast(c0[3] + b2v[0][1]);
                    float z11 = tanh_fast(c1[1] + b2v[1][0]);
                    float z13 = tanh_fast(c1[3] + b2v[1][1]);
                    po = z01 * dvO[gid] + z03 * dvO[gid + 8] + z11 * dvO[gid + 16] + z13 * dvO[gid + 24];
                }
                #pragma unroll
                for (int m = 4; m < 32; m <<= 1) {
                    pe += __shfl_xor_sync(0xffffffffu, pe, m);
                    po += __shfl_xor_sync(0xffffffffu, po, m);
                }
                // stage k locally: kstage[destBatch][wid]
                if (lane < 4) {
                    S->kstage[2 * tig][wid]     = pe;
                    S->kstage[2 * tig + 1][wid] = po;
                }
            }
            __syncthreads();
            if (wid == 0 && lane < 8) {
                fence_pa();
                bulk_s2s(dstK + (uint32_t)(stg * 512), srcK, 64, mbK);
            }

            // k wait + stage update (updater half only)
            if (tid < NH) {
                mbar_wait(kbar_a, kpar);
                if (tid == 0) mbar_expect(kbar_a, 512);
                float kv = S->kst[stg][tid] * dtv;
                S->kst[stg][tid] = kv;
                if (stg == 0)      S->ytmp[tid] = S->y[tid] + 0.5f  * kv;
                else if (stg == 1) S->ytmp[tid] = S->y[tid] + 0.75f * kv;
                else {
                    float yn = (2.0f / 9.0f) * S->kst[0][tid]
                             + (1.0f / 3.0f) * S->kst[1][tid]
                             + (4.0f / 9.0f) * kv;
                    yn = yn * dtv + S->y[tid];
                    S->y[tid] = yn;
                    float part = yn * S->lwv[tid];
                    #pragma unroll
                    for (int o = 16; o > 0; o >>= 1)
                        part += __shfl_down_sync(0xffffffffu, part, o);
                    if (lane == 0) S->red[wid] = part;
                }
            }
            kpar ^= 1;
        }
    }
    __syncthreads();
    if (tid == 0) {
        float v = S->red[0] + S->red[1] + S->red[2] + S->red[3] + lbv;
        out[(size_t)batch * NT + NT - 1] = 1.0f / (1.0f + expf(-v));
    }
    CLUSTER_SYNC();
}

extern "C" void kernel_launch(void* const* d_in, const int* in_sizes, int n_in,
                              void* d_out, int out_size) {
    const float* ts  = (const float*)d_in[0];
    const float* cd  = (const float*)d_in[1];
    const float* cc  = (const float*)d_in[2];
    const float* cb  = (const float*)d_in[3];
    const float* ca  = (const float*)d_in[4];
    const float* iW0 = (const float*)d_in[5];
    const float* ib0 = (const float*)d_in[6];
    const float* iW1 = (const float*)d_in[7];
    const float* ib1 = (const float*)d_in[8];
    const float* iW2 = (const float*)d_in[9];
    const float* ib2 = (const float*)d_in[10];
    const float* fW0 = (const float*)d_in[11];
    const float* fb0 = (const float*)d_in[12];
    const float* fW1 = (const float*)d_in[13];
    const float* fb1 = (const float*)d_in[14];
    const float* fW2 = (const float*)d_in[15];
    const float* fb2 = (const float*)d_in[16];
    const float* lW  = (const float*)d_in[17];
    const float* lb  = (const float*)d_in[18];
    float* o = (float*)d_out;

    prep_deriv<<<dim3(NB, NT / 16), 512>>>(ts, cd, cc, cb);
    cudaFuncSetAttribute(cde_kernel, cudaFuncAttributeMaxDynamicSharedMemorySize,
                         (int)sizeof(SM));
    cde_kernel<<<NB, NTHR, sizeof(SM)>>>(ts, ca,
                                         iW0, ib0, iW1, ib1, iW2, ib2,
                                         fW0, fb0, fW1, fb1, fW2, fb2,
                                         lW, lb, o);
}

// round 9
// speedup vs baseline: 1.1756x; 1.1756x over previous
#include <cuda_runtime.h>
#include <cuda_fp16.h>
#include <cstdint>
#include <cstddef>

#define NT 512
#define NH 128
#define ND 32
#define CS 8
#define NTHR 512
#define NB 64
#define DSTR 34

__device__ float g_deriv[(size_t)NT * 3 * NB * ND];

__global__ void prep_deriv(const float* __restrict__ ts, const float* __restrict__ cd,
                           const float* __restrict__ cc, const float* __restrict__ cb) {
    int b = blockIdx.x, chunk = blockIdx.y;
    int sl = threadIdx.x >> 5, d = threadIdx.x & 31;
    int s = chunk * 16 + sl;
    __shared__ float tsv[NT];
    for (int i = threadIdx.x; i < NT; i += 512) tsv[i] = ts[(size_t)b * NT + i];
    __syncthreads();
    float dt = tsv[1] - tsv[0], t0 = tsv[0];
    for (int i = 0; i < s; ++i) t0 += dt;          // exact fp32 carry, matches scan
    for (int stg = 0; stg < 3; ++stg) {
        float te = (stg == 0) ? t0 : ((stg == 1) ? t0 + 0.5f * dt : t0 + 0.75f * dt);
        int idx = 0;
        #pragma unroll
        for (int stp = 256; stp > 0; stp >>= 1) {
            int c2 = idx + stp;
            if (c2 < NT && tsv[c2] <= te) idx = c2;
        }
        if (idx > NT - 2) idx = NT - 2;
        float fr = te - tsv[idx];
        size_t off = ((size_t)b * (NT - 1) + idx) * ND + d;
        g_deriv[(((size_t)s * 3 + stg) * NB + b) * ND + d] =
            cb[off] + fr * (2.0f * cc[off] + fr * 3.0f * cd[off]);
    }
}

struct __align__(16) SM {
    uint32_t W0p[128 * 68];        // 34816 B  row-major halfs, 68-word row stride
    uint32_t W1p[128 * 68];        // 34816 B
    uint32_t BtA[8 * 68];          //  2176 B  MMA B tile (yin, then h2)
    uint32_t BtB[8 * 68];          //  2176 B  MMA B tile (h1)
    float    y[8 * 128];           //  4096 B  replicated state, all cluster batches
    float    kst[2][3][8 * 128];   // 24576 B  step-parity double-buffered raw k
    float    drv[2][3][8 * DSTR];  //  6528 B
    float    b0v[128], b1v[128], lwv[128];
    float    a0s[32];
    unsigned long long kbar;
};

__device__ __forceinline__ uint32_t smem_u32(const void* p) {
    uint32_t a;
    asm("{ .reg .u64 t; cvta.to.shared.u64 t, %1; cvt.u32.u64 %0, t; }" : "=r"(a) : "l"(p));
    return a;
}
__device__ __forceinline__ uint32_t mapa_u32(uint32_t addr, uint32_t rank) {
    uint32_t r;
    asm("mapa.shared::cluster.u32 %0, %1, %2;" : "=r"(r) : "r"(addr), "r"(rank));
    return r;
}
__device__ __forceinline__ void st_async32(uint32_t ra, uint32_t v, uint32_t rb) {
    asm volatile("st.async.shared::cluster.mbarrier::complete_tx::bytes.b32 [%0], %1, [%2];"
                 :: "r"(ra), "r"(v), "r"(rb) : "memory");
}
__device__ __forceinline__ void mbar_init(uint32_t mb, uint32_t cnt) {
    asm volatile("mbarrier.init.shared.b64 [%0], %1;" :: "r"(mb), "r"(cnt) : "memory");
}
__device__ __forceinline__ void mbar_expect(uint32_t mb, uint32_t tx) {
    asm volatile("mbarrier.arrive.expect_tx.shared::cta.b64 _, [%0], %1;"
                 :: "r"(mb), "r"(tx) : "memory");
}
__device__ __forceinline__ void mbar_wait(uint32_t mb, uint32_t parity) {
    uint32_t done;
    asm volatile("{\n\t.reg .pred p;\n\t"
                 "mbarrier.try_wait.parity.acquire.cluster.shared::cta.b64 p, [%1], %2;\n\t"
                 "selp.b32 %0, 1, 0, p;\n\t}" : "=r"(done) : "r"(mb), "r"(parity) : "memory");
    if (!done) {
        asm volatile("{\n\t.reg .pred P1;\n\t"
                     "WL_%=:\n\t"
                     "mbarrier.try_wait.parity.acquire.cluster.shared::cta.b64 P1, [%0], %1, 0x989680;\n\t"
                     "@P1 bra.uni WD_%=;\n\t"
                     "bra.uni WL_%=;\n\t"
                     "WD_%=:\n\t}" :: "r"(mb), "r"(parity) : "memory");
    }
}
#define CLUSTER_SYNC() do { \
    asm volatile("barrier.cluster.arrive.aligned;" ::: "memory"); \
    asm volatile("barrier.cluster.wait.aligned;"   ::: "memory"); } while (0)

__device__ __forceinline__ void mma16816(float* c, const uint32_t* a, uint32_t b0, uint32_t b1) {
    asm volatile("mma.sync.aligned.m16n8k16.row.col.f32.f16.f16.f32 "
                 "{%0,%1,%2,%3}, {%4,%5,%6,%7}, {%8,%9}, {%0,%1,%2,%3};"
                 : "+f"(c[0]), "+f"(c[1]), "+f"(c[2]), "+f"(c[3])
                 : "r"(a[0]), "r"(a[1]), "r"(a[2]), "r"(a[3]), "r"(b0), "r"(b1));
}
__device__ __forceinline__ float tanh_fast(float x) {
    float y; asm("tanh.approx.f32 %0, %1;" : "=f"(y) : "f"(x)); return y;
}
__device__ __forceinline__ float sp_f(float x) {
    float e = __expf(-fabsf(x));
    return fmaxf(x, 0.0f) + __logf(1.0f + e);
}
__device__ __forceinline__ uint32_t pack_h2(float a, float b) {
    __half2 h = __floats2half2_rn(a, b);
    return *reinterpret_cast<uint32_t*>(&h);
}
__device__ __forceinline__ void sth(char* base, int b, int h, float v) {
    *reinterpret_cast<__half*>(base + ((b * 68 + (h >> 1)) << 2) + ((h & 1) << 1)) = __float2half(v);
}

__global__ void __launch_bounds__(NTHR, 1) __cluster_dims__(CS, 1, 1)
cde_kernel(const float* __restrict__ ts, const float* __restrict__ ca,
           const float* __restrict__ iW0, const float* __restrict__ ib0,
           const float* __restrict__ iW1, const float* __restrict__ ib1,
           const float* __restrict__ iW2, const float* __restrict__ ib2,
           const float* __restrict__ fW0, const float* __restrict__ fb0,
           const float* __restrict__ fW1, const float* __restrict__ fb1,
           const float* __restrict__ fW2, const float* __restrict__ fb2,
           const float* __restrict__ lW, const float* __restrict__ lb,
           float* __restrict__ out)
{
    extern __shared__ char smraw[];
    SM* S = reinterpret_cast<SM*>(smraw);
    const int tid = threadIdx.x, wid = tid >> 5, lane = tid & 31;
    const int gid = lane >> 2, tig = lane & 3;
    const int batch = blockIdx.x;
    const int rank = batch & (CS - 1), cbat0 = batch & ~(CS - 1);

    const uint32_t y_a    = smem_u32(&S->y[0]);
    const uint32_t kst_a  = smem_u32(&S->kst[0][0][0]);
    const uint32_t kbar_a = smem_u32(&S->kbar);

    if (tid == 0) {
        mbar_init(kbar_a, 1);
        mbar_expect(kbar_a, 4096);
        asm volatile("fence.mbarrier_init.release.cluster;" ::: "memory");
    }

    // ---- weights to SMEM: row-major halfs, 68-word padded rows (conflict-free) ----
    for (int i = tid; i < 128 * 64; i += NTHR) {
        int row = i >> 6, w = i & 63;
        S->W0p[row * 68 + w] = pack_h2(fW0[row * NH + 2 * w], fW0[row * NH + 2 * w + 1]);
        S->W1p[row * 68 + w] = pack_h2(fW1[row * NH + 2 * w], fW1[row * NH + 2 * w + 1]);
    }
    if (tid < NH) { S->b0v[tid] = fb0[tid]; S->b1v[tid] = fb1[tid]; S->lwv[tid] = lW[tid]; }

    // ---- register-resident W2 frags: warp owns h = rank*16 + wid (32 rows) ----
    const int rowbase = rank * 512 + wid * 32;
    uint32_t areg[2][8][4];
    float b2v[2][2];
    #pragma unroll
    for (int t = 0; t < 2; ++t) {
        int r0g = rowbase + t * 16 + gid, r1g = r0g + 8;
        b2v[t][0] = fb2[r0g]; b2v[t][1] = fb2[r1g];
        #pragma unroll
        for (int ks = 0; ks < 8; ++ks) {
            int c0 = ks * 16 + 2 * tig;
            const float* w0 = fW2 + (size_t)r0g * NH;
            const float* w1 = fW2 + (size_t)r1g * NH;
            areg[t][ks][0] = pack_h2(w0[c0], w0[c0 + 1]);
            areg[t][ks][1] = pack_h2(w1[c0], w1[c0 + 1]);
            areg[t][ks][2] = pack_h2(w0[c0 + 8], w0[c0 + 9]);
            areg[t][ks][3] = pack_h2(w1[c0 + 8], w1[c0 + 9]);
        }
    }
    __syncthreads();

    // ---- initial MLP (fp32, exact, own batch) using BtA/BtB as f32 scratch ----
    float* sc1 = reinterpret_cast<float*>(S->BtA);
    float* sc2 = reinterpret_cast<float*>(S->BtB);
    if (tid < ND) S->a0s[tid] = ca[(size_t)batch * (NT - 1) * ND + tid];
    __syncthreads();
    if (tid < NH) {
        float a = ib0[tid];
        #pragma unroll
        for (int k = 0; k < ND; ++k) a = fmaf(iW0[tid * ND + k], S->a0s[k], a);
        sc1[tid] = fmaxf(a, 0.0f);
    }
    __syncthreads();
    if (tid < NH) {
        float a = ib1[tid];
        for (int k = 0; k < NH; ++k) a = fmaf(iW1[tid * NH + k], sc1[k], a);
        sc2[tid] = fmaxf(a, 0.0f);
    }
    __syncthreads();
    float y0v = 0.0f;
    if (tid < NH) {
        float a = ib2[tid];
        for (int k = 0; k < NH; ++k) a = fmaf(iW2[tid * NH + k], sc2[k], a);
        y0v = a;
    }
    // derivs for s=0
    if (tid < 192) {
        int stgp = tid >> 6, r = tid & 63, b = r >> 3, seg = r & 7;
        float4 v = *(const float4*)&g_deriv[(((size_t)0 * 3 + stgp) * NB + cbat0 + b) * ND + seg * 4];
        float* dp = &S->drv[0][stgp][b * DSTR + seg * 4];
        *(float2*)dp = make_float2(v.x, v.y);
        *(float2*)(dp + 2) = make_float2(v.z, v.w);
    }
    __syncthreads();
    CLUSTER_SYNC();

    // ---- broadcast y0 to all peers (incl. self) through kbar, acts as phase 0 ----
    if (tid < NH) {
        uint32_t off = y_a + (uint32_t)((rank * 128 + tid) << 2);
        #pragma unroll
        for (int pr = 0; pr < CS; ++pr)
            st_async32(mapa_u32(off, pr), __float_as_uint(y0v), mapa_u32(kbar_a, pr));
    }

    const float dtv = ts[(size_t)batch * NT + 1] - ts[(size_t)batch * NT];
    const float lbv = lb[0];
    uint32_t kpar = 0;
    const int pb = tid >> 6, pw = tid & 63;   // pack mapping
    const int hidx = rank * 16 + wid;

    for (int s = 0; s < NT; ++s) {
        const int p = s & 1;
        const float* dbuf = &S->drv[p][0][0];
        #pragma unroll 1
        for (int stg = 0; stg < 3; ++stg) {
            // ---- wait for k (or y0) delivery ----
            mbar_wait(kbar_a, kpar); kpar ^= 1;
            if (tid == 0) mbar_expect(kbar_a, 4096);

            // ---- pack phase: yin -> BtA (fp16 B-tile), fold RK update ----
            {
                float* yrow = &S->y[pb * 128 + 2 * pw];
                float2 yv = *(const float2*)yrow;
                float2 yn;
                if (stg == 0) {
                    if (s > 0) {
                        const float* kp0 = &S->kst[1 - p][0][pb * 128 + 2 * pw];
                        float2 k0 = *(const float2*)kp0;
                        float2 k1 = *(const float2*)(kp0 + 1024);
                        float2 k2 = *(const float2*)(kp0 + 2048);
                        float cx = fmaf(4.f/9.f, k2.x * dtv, fmaf(1.f/3.f, k1.x * dtv, (2.f/9.f) * (k0.x * dtv)));
                        float cy = fmaf(4.f/9.f, k2.y * dtv, fmaf(1.f/3.f, k1.y * dtv, (2.f/9.f) * (k0.y * dtv)));
                        yn.x = fmaf(cx, dtv, yv.x);
                        yn.y = fmaf(cy, dtv, yv.y);
                        *(float2*)yrow = yn;
                    } else yn = yv;
                } else {
                    const float* kp0 = &S->kst[p][stg - 1][pb * 128 + 2 * pw];
                    float2 kq = *(const float2*)kp0;
                    float cf = (stg == 1) ? 0.5f : 0.75f;
                    yn.x = fmaf(kq.x * dtv, cf, yv.x);
                    yn.y = fmaf(kq.y * dtv, cf, yv.y);
                }
                S->BtA[pb * 68 + pw] = pack_h2(yn.x, yn.y);
            }
            __syncthreads();

            // ---- parallel phase: L1 (w0-7) | output (w8, stg0) | deriv pf (w10-15, stg0) ----
            if (wid < 8) {
                float cc[4];
                int h0 = (wid << 4) + gid;
                cc[0] = cc[1] = S->b0v[h0];
                cc[2] = cc[3] = S->b0v[h0 + 8];
                #pragma unroll
                for (int ks = 0; ks < 8; ++ks) {
                    uint32_t a[4];
                    const uint32_t* r0 = S->W0p + (h0) * 68 + ks * 8 + tig;
                    const uint32_t* r1 = S->W0p + (h0 + 8) * 68 + ks * 8 + tig;
                    a[0] = r0[0]; a[1] = r1[0]; a[2] = r0[4]; a[3] = r1[4];
                    uint32_t b0 = S->BtA[gid * 68 + ks * 8 + tig];
                    uint32_t b1 = S->BtA[gid * 68 + ks * 8 + tig + 4];
                    mma16816(cc, a, b0, b1);
                }
                char* bb = reinterpret_cast<char*>(S->BtB);
                sth(bb, 2 * tig,     h0,     sp_f(cc[0]));
                sth(bb, 2 * tig + 1, h0,     sp_f(cc[1]));
                sth(bb, 2 * tig,     h0 + 8, sp_f(cc[2]));
                sth(bb, 2 * tig + 1, h0 + 8, sp_f(cc[3]));
            } else if (wid == 8 && stg == 0 && s > 0) {
                const float* yb = &S->y[rank * 128];
                float a = yb[lane] * S->lwv[lane];
                a = fmaf(yb[lane + 32], S->lwv[lane + 32], a);
                a = fmaf(yb[lane + 64], S->lwv[lane + 64], a);
                a = fmaf(yb[lane + 96], S->lwv[lane + 96], a);
                #pragma unroll
                for (int o = 16; o > 0; o >>= 1) a += __shfl_down_sync(0xffffffffu, a, o);
                if (lane == 0)
                    out[(size_t)batch * NT + s - 1] = 1.0f / (1.0f + expf(-(a + lbv)));
            } else if (stg == 0 && tid >= 320) {
                int s1 = (s + 1 < NT) ? s + 1 : NT - 1;
                int r = tid - 320;
                int stgp = r >> 6, rr = r & 63, b = rr >> 3, seg = rr & 7;
                float4 v = *(const float4*)&g_deriv[(((size_t)s1 * 3 + stgp) * NB + cbat0 + b) * ND + seg * 4];
                float* dp = &S->drv[1 - p][stgp][b * DSTR + seg * 4];
                *(float2*)dp = make_float2(v.x, v.y);
                *(float2*)(dp + 2) = make_float2(v.z, v.w);
            }
            __syncthreads();

            // ---- L2 (w0-7): BtB -> h2 into BtA ----
            if (wid < 8) {
                float cc[4];
                int h0 = (wid << 4) + gid;
                cc[0] = cc[1] = S->b1v[h0];
                cc[2] = cc[3] = S->b1v[h0 + 8];
                #pragma unroll
                for (int ks = 0; ks < 8; ++ks) {
                    uint32_t a[4];
                    const uint32_t* r0 = S->W1p + (h0) * 68 + ks * 8 + tig;
                    const uint32_t* r1 = S->W1p + (h0 + 8) * 68 + ks * 8 + tig;
                    a[0] = r0[0]; a[1] = r1[0]; a[2] = r0[4]; a[3] = r1[4];
                    uint32_t b0 = S->BtB[gid * 68 + ks * 8 + tig];
                    uint32_t b1 = S->BtB[gid * 68 + ks * 8 + tig + 4];
                    mma16816(cc, a, b0, b1);
                }
                char* bb = reinterpret_cast<char*>(S->BtA);
                sth(bb, 2 * tig,     h0,     sp_f(cc[0]));
                sth(bb, 2 * tig + 1, h0,     sp_f(cc[1]));
                sth(bb, 2 * tig,     h0 + 8, sp_f(cc[2]));
                sth(bb, 2 * tig + 1, h0 + 8, sp_f(cc[3]));
            }
            __syncthreads();

            // ---- L3 (all 16 warps): W2 HMMA + epilogue + k all-gather ----
            {
                float c0[4] = {0.f, 0.f, 0.f, 0.f};
                float c1[4] = {0.f, 0.f, 0.f, 0.f};
                #pragma unroll
                for (int ks = 0; ks < 8; ++ks) {
                    uint32_t b0 = S->BtA[gid * 68 + ks * 8 + tig];
                    uint32_t b1 = S->BtA[gid * 68 + ks * 8 + tig + 4];
                    mma16816(c0, areg[0][ks], b0, b1);
                    mma16816(c1, areg[1][ks], b0, b1);
                }
                const float* dvE = dbuf + stg * (CS * DSTR) + (2 * tig) * DSTR;
                const float* dvO = dvE + DSTR;
                float pe, po;
                {
                    float z00 = tanh_fast(c0[0] + b2v[0][0]);
                    float z02 = tanh_fast(c0[2] + b2v[0][1]);
                    float z10 = tanh_fast(c1[0] + b2v[1][0]);
                    float z12 = tanh_fast(c1[2] + b2v[1][1]);
                    pe = z00 * dvE[gid] + z02 * dvE[gid + 8] + z10 * dvE[gid + 16] + z12 * dvE[gid + 24];
                    float z01 = tanh_fast(c0[1] + b2v[0][0]);
                    float z03 = tanh_fast(c0[3] + b2v[0][1]);
                    float z11 = tanh_fast(c1[1] + b2v[1][0]);
                    float z13 = tanh_fast(c1[3] + b2v[1][1]);
                    po = z01 * dvO[gid] + z03 * dvO[gid + 8] + z11 * dvO[gid + 16] + z13 * dvO[gid + 24];
                }
                #pragma unroll
                for (int m = 4; m < 32; m <<= 1) {
                    pe += __shfl_xor_sync(0xffffffffu, pe, m);
                    po += __shfl_xor_sync(0xffffffffu, po, m);
                }
                if (lane < 4) {
                    uint32_t offE = kst_a + (uint32_t)((((p * 3 + stg) * 8 + 2 * tig) * 128 + hidx) << 2);
                    uint32_t offO = offE + (128 << 2);
                    #pragma unroll
                    for (int pr = 0; pr < CS; ++pr) {
                        uint32_t rb = mapa_u32(kbar_a, pr);
                        st_async32(mapa_u32(offE, pr), __float_as_uint(pe), rb);
                        st_async32(mapa_u32(offO, pr), __float_as_uint(po), rb);
                    }
                }
            }
        }
    }

    // ---- final: wait last k, update y, write out[NT-1] ----
    mbar_wait(kbar_a, kpar);
    {
        const int p = (NT - 1) & 1;
        float* yrow = &S->y[pb * 128 + 2 * pw];
        float2 yv = *(const float2*)yrow;
        const float* kp0 = &S->kst[p][0][pb * 128 + 2 * pw];
        float2 k0 = *(const float2*)kp0;
        float2 k1 = *(const float2*)(kp0 + 1024);
        float2 k2 = *(const float2*)(kp0 + 2048);
        float cx = fmaf(4.f/9.f, k2.x * dtv, fmaf(1.f/3.f, k1.x * dtv, (2.f/9.f) * (k0.x * dtv)));
        float cy = fmaf(4.f/9.f, k2.y * dtv, fmaf(1.f/3.f, k1.y * dtv, (2.f/9.f) * (k0.y * dtv)));
        yv.x = fmaf(cx, dtv, yv.x);
        yv.y = fmaf(cy, dtv, yv.y);
        *(float2*)yrow = yv;
    }
    __syncthreads();
    if (wid == 8) {
        const float* yb = &S->y[rank * 128];
        float a = yb[lane] * S->lwv[lane];
        a = fmaf(yb[lane + 32], S->lwv[lane + 32], a);
        a = fmaf(yb[lane + 64], S->lwv[lane + 64], a);
        a = fmaf(yb[lane + 96], S->lwv[lane + 96], a);
        #pragma unroll
        for (int o = 16; o > 0; o >>= 1) a += __shfl_down_sync(0xffffffffu, a, o);
        if (lane == 0)
            out[(size_t)batch * NT + NT - 1] = 1.0f / (1.0f + expf(-(a + lbv)));
    }
    CLUSTER_SYNC();
}

extern "C" void kernel_launch(void* const* d_in, const int* in_sizes, int n_in,
                              void* d_out, int out_size) {
    const float* ts  = (const float*)d_in[0];
    const float* cd  = (const float*)d_in[1];
    const float* cc  = (const float*)d_in[2];
    const float* cb  = (const float*)d_in[3];
    const float* ca  = (const float*)d_in[4];
    const float* iW0 = (const float*)d_in[5];
    const float* ib0 = (const float*)d_in[6];
    const float* iW1 = (const float*)d_in[7];
    const float* ib1 = (const float*)d_in[8];
    const float* iW2 = (const float*)d_in[9];
    const float* ib2 = (const float*)d_in[10];
    const float* fW0 = (const float*)d_in[11];
    const float* fb0 = (const float*)d_in[12];
    const float* fW1 = (const float*)d_in[13];
    const float* fb1 = (const float*)d_in[14];
    const float* fW2 = (const float*)d_in[15];
    const float* fb2 = (const float*)d_in[16];
    const float* lW  = (const float*)d_in[17];
    const float* lb  = (const float*)d_in[18];
    float* o = (float*)d_out;

    prep_deriv<<<dim3(NB, NT / 16), 512>>>(ts, cd, cc, cb);
    cudaFuncSetAttribute(cde_kernel, cudaFuncAttributeMaxDynamicSharedMemorySize,
                         (int)sizeof(SM));
    cde_kernel<<<NB, NTHR, sizeof(SM)>>>(ts, ca,
                                         iW0, ib0, iW1, ib1, iW2, ib2,
                                         fW0, fb0, fW1, fb1, fW2, fb2,
                                         lW, lb, o);
}

// round 10
// speedup vs baseline: 1.6222x; 1.3799x over previous
#include <cuda_runtime.h>
#include <cuda_fp16.h>
#include <cstdint>
#include <cstddef>

#define NT 512
#define NH 128
#define ND 32
#define CS 8
#define NTHR 512
#define NB 64
#define DSTR 34

__device__ float g_deriv[(size_t)NT * 3 * NB * ND];

__global__ void prep_deriv(const float* __restrict__ ts, const float* __restrict__ cd,
                           const float* __restrict__ cc, const float* __restrict__ cb) {
    int b = blockIdx.x, chunk = blockIdx.y;
    int sl = threadIdx.x >> 5, d = threadIdx.x & 31;
    int s = chunk * 16 + sl;
    __shared__ float tsv[NT];
    for (int i = threadIdx.x; i < NT; i += 512) tsv[i] = ts[(size_t)b * NT + i];
    __syncthreads();
    float dt = tsv[1] - tsv[0], t0 = tsv[0];
    for (int i = 0; i < s; ++i) t0 += dt;          // exact fp32 carry, matches scan
    for (int stg = 0; stg < 3; ++stg) {
        float te = (stg == 0) ? t0 : ((stg == 1) ? t0 + 0.5f * dt : t0 + 0.75f * dt);
        int idx = 0;
        #pragma unroll
        for (int stp = 256; stp > 0; stp >>= 1) {
            int c2 = idx + stp;
            if (c2 < NT && tsv[c2] <= te) idx = c2;
        }
        if (idx > NT - 2) idx = NT - 2;
        float fr = te - tsv[idx];
        size_t off = ((size_t)b * (NT - 1) + idx) * ND + d;
        g_deriv[(((size_t)s * 3 + stg) * NB + b) * ND + d] =
            cb[off] + fr * (2.0f * cc[off] + fr * 3.0f * cd[off]);
    }
}

struct __align__(16) SM {
    uint32_t W0p[128 * 68];
    uint32_t W1p[128 * 68];
    uint32_t BtA[8 * 68];
    uint32_t BtB[8 * 68];
    float2   y2[64 * 8];           // y state [hpair][batch]
    float    y_lin[128];           // own-batch linear copy
    __half   kh[2][3][128 * 8];    // received k, fp16, [parity][stg][h][batch]
    float    drv[2][3][8 * DSTR];
    float    b0v[128], b1v[128], lwv[128];
    float    a0s[32];
    unsigned long long kbar;
};

__device__ __forceinline__ uint32_t smem_u32(const void* p) {
    uint32_t a;
    asm("{ .reg .u64 t; cvta.to.shared.u64 t, %1; cvt.u32.u64 %0, t; }" : "=r"(a) : "l"(p));
    return a;
}
__device__ __forceinline__ uint32_t mapa_u32(uint32_t addr, uint32_t rank) {
    uint32_t r;
    asm("mapa.shared::cluster.u32 %0, %1, %2;" : "=r"(r) : "r"(addr), "r"(rank));
    return r;
}
__device__ __forceinline__ void st_async64(uint32_t ra, uint64_t v, uint32_t rb) {
    asm volatile("st.async.shared::cluster.mbarrier::complete_tx::bytes.b64 [%0], %1, [%2];"
                 :: "r"(ra), "l"(v), "r"(rb) : "memory");
}
__device__ __forceinline__ void mbar_init(uint32_t mb, uint32_t cnt) {
    asm volatile("mbarrier.init.shared.b64 [%0], %1;" :: "r"(mb), "r"(cnt) : "memory");
}
__device__ __forceinline__ void mbar_expect(uint32_t mb, uint32_t tx) {
    asm volatile("mbarrier.arrive.expect_tx.shared::cta.b64 _, [%0], %1;"
                 :: "r"(mb), "r"(tx) : "memory");
}
__device__ __forceinline__ void mbar_wait(uint32_t mb, uint32_t parity) {
    uint32_t done;
    asm volatile("{\n\t.reg .pred p;\n\t"
                 "mbarrier.try_wait.parity.acquire.cluster.shared::cta.b64 p, [%1], %2;\n\t"
                 "selp.b32 %0, 1, 0, p;\n\t}" : "=r"(done) : "r"(mb), "r"(parity) : "memory");
    if (!done) {
        asm volatile("{\n\t.reg .pred P1;\n\t"
                     "WL_%=:\n\t"
                     "mbarrier.try_wait.parity.acquire.cluster.shared::cta.b64 P1, [%0], %1, 0x989680;\n\t"
                     "@P1 bra.uni WD_%=;\n\t"
                     "bra.uni WL_%=;\n\t"
                     "WD_%=:\n\t}" :: "r"(mb), "r"(parity) : "memory");
    }
}
#define CLUSTER_SYNC() do { \
    asm volatile("barrier.cluster.arrive.aligned;" ::: "memory"); \
    asm volatile("barrier.cluster.wait.aligned;"   ::: "memory"); } while (0)

__device__ __forceinline__ void mma16816(float* c, const uint32_t* a, uint32_t b0, uint32_t b1) {
    asm volatile("mma.sync.aligned.m16n8k16.row.col.f32.f16.f16.f32 "
                 "{%0,%1,%2,%3}, {%4,%5,%6,%7}, {%8,%9}, {%0,%1,%2,%3};"
                 : "+f"(c[0]), "+f"(c[1]), "+f"(c[2]), "+f"(c[3])
                 : "r"(a[0]), "r"(a[1]), "r"(a[2]), "r"(a[3]), "r"(b0), "r"(b1));
}
__device__ __forceinline__ float tanh_fast(float x) {
    float y; asm("tanh.approx.f32 %0, %1;" : "=f"(y) : "f"(x)); return y;
}
__device__ __forceinline__ float sp_f(float x) {
    float e = __expf(-fabsf(x));
    return fmaxf(x, 0.0f) + __logf(1.0f + e);
}
__device__ __forceinline__ uint32_t pack_h2(float a, float b) {
    __half2 h = __floats2half2_rn(a, b);
    return *reinterpret_cast<uint32_t*>(&h);
}
__device__ __forceinline__ void sth(char* base, int b, int h, float v) {
    *reinterpret_cast<__half*>(base + ((b * 68 + (h >> 1)) << 2) + ((h & 1) << 1)) = __float2half(v);
}

__global__ void __launch_bounds__(NTHR, 1) __cluster_dims__(CS, 1, 1)
cde_kernel(const float* __restrict__ ts, const float* __restrict__ ca,
           const float* __restrict__ iW0, const float* __restrict__ ib0,
           const float* __restrict__ iW1, const float* __restrict__ ib1,
           const float* __restrict__ iW2, const float* __restrict__ ib2,
           const float* __restrict__ fW0, const float* __restrict__ fb0,
           const float* __restrict__ fW1, const float* __restrict__ fb1,
           const float* __restrict__ fW2, const float* __restrict__ fb2,
           const float* __restrict__ lW, const float* __restrict__ lb,
           float* __restrict__ out)
{
    extern __shared__ char smraw[];
    SM* S = reinterpret_cast<SM*>(smraw);
    const int tid = threadIdx.x, wid = tid >> 5, lane = tid & 31;
    const int gid = lane >> 2, tig = lane & 3;
    const int batch = blockIdx.x;
    const int rank = batch & (CS - 1), cbat0 = batch & ~(CS - 1);

    const uint32_t y2_a   = smem_u32(&S->y2[0]);
    const uint32_t kh_a   = smem_u32(&S->kh[0][0][0]);
    const uint32_t kbar_a = smem_u32(&S->kbar);

    if (tid == 0) {
        mbar_init(kbar_a, 1);
        mbar_expect(kbar_a, 4096);   // phase 0: y0 broadcast (8 CTAs x 512 B)
        asm volatile("fence.mbarrier_init.release.cluster;" ::: "memory");
    }

    for (int i = tid; i < 128 * 64; i += NTHR) {
        int row = i >> 6, w = i & 63;
        S->W0p[row * 68 + w] = pack_h2(fW0[row * NH + 2 * w], fW0[row * NH + 2 * w + 1]);
        S->W1p[row * 68 + w] = pack_h2(fW1[row * NH + 2 * w], fW1[row * NH + 2 * w + 1]);
    }
    if (tid < NH) { S->b0v[tid] = fb0[tid]; S->b1v[tid] = fb1[tid]; S->lwv[tid] = lW[tid]; }

    const int rowbase = rank * 512 + wid * 32;
    uint32_t areg[2][8][4];
    float b2v[2][2];
    #pragma unroll
    for (int t = 0; t < 2; ++t) {
        int r0g = rowbase + t * 16 + gid, r1g = r0g + 8;
        b2v[t][0] = fb2[r0g]; b2v[t][1] = fb2[r1g];
        #pragma unroll
        for (int ks = 0; ks < 8; ++ks) {
            int c0 = ks * 16 + 2 * tig;
            const float* w0 = fW2 + (size_t)r0g * NH;
            const float* w1 = fW2 + (size_t)r1g * NH;
            areg[t][ks][0] = pack_h2(w0[c0], w0[c0 + 1]);
            areg[t][ks][1] = pack_h2(w1[c0], w1[c0 + 1]);
            areg[t][ks][2] = pack_h2(w0[c0 + 8], w0[c0 + 9]);
            areg[t][ks][3] = pack_h2(w1[c0 + 8], w1[c0 + 9]);
        }
    }
    __syncthreads();

    // initial MLP (fp32, exact) -> y0 in y_lin staging
    float* sc1 = reinterpret_cast<float*>(S->BtA);
    float* sc2 = reinterpret_cast<float*>(S->BtB);
    if (tid < ND) S->a0s[tid] = ca[(size_t)batch * (NT - 1) * ND + tid];
    __syncthreads();
    if (tid < NH) {
        float a = ib0[tid];
        #pragma unroll
        for (int k = 0; k < ND; ++k) a = fmaf(iW0[tid * ND + k], S->a0s[k], a);
        sc1[tid] = fmaxf(a, 0.0f);
    }
    __syncthreads();
    if (tid < NH) {
        float a = ib1[tid];
        for (int k = 0; k < NH; ++k) a = fmaf(iW1[tid * NH + k], sc1[k], a);
        sc2[tid] = fmaxf(a, 0.0f);
    }
    __syncthreads();
    if (tid < NH) {
        float a = ib2[tid];
        for (int k = 0; k < NH; ++k) a = fmaf(iW2[tid * NH + k], sc2[k], a);
        S->y_lin[tid] = a;
    }
    if (tid < 192) {   // derivs for s=0
        int stgp = tid >> 6, r = tid & 63, b = r >> 3, seg = r & 7;
        float4 v = *(const float4*)&g_deriv[(((size_t)0 * 3 + stgp) * NB + cbat0 + b) * ND + seg * 4];
        float* dp = &S->drv[0][stgp][b * DSTR + seg * 4];
        *(float2*)dp = make_float2(v.x, v.y);
        *(float2*)(dp + 2) = make_float2(v.z, v.w);
    }
    __syncthreads();
    CLUSTER_SYNC();

    // y0 broadcast: thread t<64 sends own-batch float2 to y2[t][rank] of all peers
    if (tid < 64) {
        float2 yv = *(const float2*)&S->y_lin[2 * tid];
        uint64_t pay;
        memcpy(&pay, &yv, 8);
        uint32_t off = y2_a + (uint32_t)((tid * 8 + rank) << 3);
        #pragma unroll
        for (int pr = 0; pr < CS; ++pr)
            st_async64(mapa_u32(off, pr), pay, mapa_u32(kbar_a, pr));
    }

    const float dtv = ts[(size_t)batch * NT + 1] - ts[(size_t)batch * NT];
    const float lbv = lb[0];
    uint32_t kpar = 0;
    const int pb = tid & 7, hp = tid >> 3;   // pack mapping: batch, h-pair
    const int hidx = rank * 16 + wid;

    for (int s = 0; s < NT; ++s) {
        const int p = s & 1;
        const float* dbuf = &S->drv[p][0][0];
        #pragma unroll 1
        for (int stg = 0; stg < 3; ++stg) {
            float4 pf;
            const bool dopf = (stg == 0) && (tid >= 320);
            if (dopf) {   // prefetch issued BEFORE the wait (latency hidden)
                int s1 = (s + 1 < NT) ? s + 1 : NT - 1;
                int r = tid - 320;
                int stgp = r >> 6, rr = r & 63, b = rr >> 3, seg = rr & 7;
                pf = *(const float4*)&g_deriv[(((size_t)s1 * 3 + stgp) * NB + cbat0 + b) * ND + seg * 4];
            }
            mbar_wait(kbar_a, kpar); kpar ^= 1;
            if (tid == 0) mbar_expect(kbar_a, 2048);

            // ---- pack: yin -> BtA, fold RK update (thread owns (hp, pb)) ----
            {
                float2 yv = S->y2[hp * 8 + pb];
                float2 yn;
                const __half* kb;
                if (stg == 0) {
                    if (s > 0) {
                        kb = &S->kh[1 - p][0][0];
                        int o0 = (2 * hp) * 8 + pb, o1 = o0 + 8;
                        float k0x = __half2float(kb[o0]),        k0y = __half2float(kb[o1]);
                        float k1x = __half2float(kb[1024 + o0]), k1y = __half2float(kb[1024 + o1]);
                        float k2x = __half2float(kb[2048 + o0]), k2y = __half2float(kb[2048 + o1]);
                        float cx = fmaf(4.f/9.f, k2x * dtv, fmaf(1.f/3.f, k1x * dtv, (2.f/9.f) * (k0x * dtv)));
                        float cy = fmaf(4.f/9.f, k2y * dtv, fmaf(1.f/3.f, k1y * dtv, (2.f/9.f) * (k0y * dtv)));
                        yn.x = fmaf(cx, dtv, yv.x);
                        yn.y = fmaf(cy, dtv, yv.y);
                        S->y2[hp * 8 + pb] = yn;
                        if (pb == rank) *(float2*)&S->y_lin[2 * hp] = yn;
                    } else yn = yv;
                } else {
                    kb = &S->kh[p][stg - 1][0];
                    int o0 = (2 * hp) * 8 + pb;
                    float kx = __half2float(kb[o0]), ky = __half2float(kb[o0 + 8]);
                    float cf = (stg == 1) ? 0.5f : 0.75f;
                    yn.x = fmaf(kx * dtv, cf, yv.x);
                    yn.y = fmaf(ky * dtv, cf, yv.y);
                }
                S->BtA[pb * 68 + hp] = pack_h2(yn.x, yn.y);
            }
            __syncthreads();

            if (wid < 8) {
                // ---- L1 ----
                float cc[4];
                int h0 = (wid << 4) + gid;
                cc[0] = cc[1] = S->b0v[h0];
                cc[2] = cc[3] = S->b0v[h0 + 8];
                #pragma unroll
                for (int ks = 0; ks < 8; ++ks) {
                    uint32_t a[4];
                    const uint32_t* r0 = S->W0p + h0 * 68 + ks * 8 + tig;
                    const uint32_t* r1 = S->W0p + (h0 + 8) * 68 + ks * 8 + tig;
                    a[0] = r0[0]; a[1] = r1[0]; a[2] = r0[4]; a[3] = r1[4];
                    mma16816(cc, a, S->BtA[gid * 68 + ks * 8 + tig], S->BtA[gid * 68 + ks * 8 + tig + 4]);
                }
                char* bb = reinterpret_cast<char*>(S->BtB);
                sth(bb, 2 * tig,     h0,     sp_f(cc[0]));
                sth(bb, 2 * tig + 1, h0,     sp_f(cc[1]));
                sth(bb, 2 * tig,     h0 + 8, sp_f(cc[2]));
                sth(bb, 2 * tig + 1, h0 + 8, sp_f(cc[3]));
                asm volatile("bar.sync 1, 256;" ::: "memory");
                // ---- L2 ----
                cc[0] = cc[1] = S->b1v[h0];
                cc[2] = cc[3] = S->b1v[h0 + 8];
                #pragma unroll
                for (int ks = 0; ks < 8; ++ks) {
                    uint32_t a[4];
                    const uint32_t* r0 = S->W1p + h0 * 68 + ks * 8 + tig;
                    const uint32_t* r1 = S->W1p + (h0 + 8) * 68 + ks * 8 + tig;
                    a[0] = r0[0]; a[1] = r1[0]; a[2] = r0[4]; a[3] = r1[4];
                    mma16816(cc, a, S->BtB[gid * 68 + ks * 8 + tig], S->BtB[gid * 68 + ks * 8 + tig + 4]);
                }
                char* ba = reinterpret_cast<char*>(S->BtA);
                sth(ba, 2 * tig,     h0,     sp_f(cc[0]));
                sth(ba, 2 * tig + 1, h0,     sp_f(cc[1]));
                sth(ba, 2 * tig,     h0 + 8, sp_f(cc[2]));
                sth(ba, 2 * tig + 1, h0 + 8, sp_f(cc[3]));
            } else if (stg == 0) {
                if (wid == 8 && s > 0) {
                    float a = S->y_lin[lane] * S->lwv[lane];
                    a = fmaf(S->y_lin[lane + 32], S->lwv[lane + 32], a);
                    a = fmaf(S->y_lin[lane + 64], S->lwv[lane + 64], a);
                    a = fmaf(S->y_lin[lane + 96], S->lwv[lane + 96], a);
                    #pragma unroll
                    for (int o = 16; o > 0; o >>= 1) a += __shfl_down_sync(0xffffffffu, a, o);
                    if (lane == 0)
                        out[(size_t)batch * NT + s - 1] = 1.0f / (1.0f + expf(-(a + lbv)));
                }
                if (dopf) {
                    int r = tid - 320;
                    int stgp = r >> 6, rr = r & 63, b = rr >> 3, seg = rr & 7;
                    float* dp = &S->drv[1 - p][stgp][b * DSTR + seg * 4];
                    *(float2*)dp = make_float2(pf.x, pf.y);
                    *(float2*)(dp + 2) = make_float2(pf.z, pf.w);
                }
            }
            __syncthreads();

            // ---- L3: W2 HMMA + epilogue + fp16 packed k all-gather ----
            {
                float c0[4] = {0.f, 0.f, 0.f, 0.f};
                float c1[4] = {0.f, 0.f, 0.f, 0.f};
                #pragma unroll
                for (int ks = 0; ks < 8; ++ks) {
                    uint32_t b0 = S->BtA[gid * 68 + ks * 8 + tig];
                    uint32_t b1 = S->BtA[gid * 68 + ks * 8 + tig + 4];
                    mma16816(c0, areg[0][ks], b0, b1);
                    mma16816(c1, areg[1][ks], b0, b1);
                }
                const float* dvE = dbuf + stg * (CS * DSTR) + (2 * tig) * DSTR;
                const float* dvO = dvE + DSTR;
                float pe, po;
                {
                    float z00 = tanh_fast(c0[0] + b2v[0][0]);
                    float z02 = tanh_fast(c0[2] + b2v[0][1]);
                    float z10 = tanh_fast(c1[0] + b2v[1][0]);
                    float z12 = tanh_fast(c1[2] + b2v[1][1]);
                    pe = z00 * dvE[gid] + z02 * dvE[gid + 8] + z10 * dvE[gid + 16] + z12 * dvE[gid + 24];
                    float z01 = tanh_fast(c0[1] + b2v[0][0]);
                    float z03 = tanh_fast(c0[3] + b2v[0][1]);
                    float z11 = tanh_fast(c1[1] + b2v[1][0]);
                    float z13 = tanh_fast(c1[3] + b2v[1][1]);
                    po = z01 * dvO[gid] + z03 * dvO[gid + 8] + z11 * dvO[gid + 16] + z13 * dvO[gid + 24];
                }
                #pragma unroll
                for (int m = 4; m < 32; m <<= 1) {
                    pe += __shfl_xor_sync(0xffffffffu, pe, m);
                    po += __shfl_xor_sync(0xffffffffu, po, m);
                }
                uint32_t b32h = pack_h2(pe, po);             // batches 2*tig, 2*tig+1
                uint32_t lo = __shfl_sync(0xffffffffu, b32h, 2 * lane);
                uint32_t hi = __shfl_sync(0xffffffffu, b32h, 2 * lane + 1);
                if (lane < 2) {
                    uint64_t pay = (uint64_t)lo | ((uint64_t)hi << 32);
                    uint32_t boff = kh_a + (uint32_t)((p * 3 + stg) * 2048 + hidx * 16 + lane * 8);
                    #pragma unroll
                    for (int pr = 0; pr < CS; ++pr)
                        st_async64(mapa_u32(boff, pr), pay, mapa_u32(kbar_a, pr));
                }
            }
        }
    }

    // ---- final: wait last k, update own batch, write out[NT-1] ----
    mbar_wait(kbar_a, kpar);
    if (tid < 64) {
        const __half* kb = &S->kh[1][0][0];   // NT-1 is odd -> p=1
        int o0 = (2 * tid) * 8 + rank, o1 = o0 + 8;
        float2 yv = S->y2[tid * 8 + rank];
        float k0x = __half2float(kb[o0]),        k0y = __half2float(kb[o1]);
        float k1x = __half2float(kb[1024 + o0]), k1y = __half2float(kb[1024 + o1]);
        float k2x = __half2float(kb[2048 + o0]), k2y = __half2float(kb[2048 + o1]);
        float cx = fmaf(4.f/9.f, k2x * dtv, fmaf(1.f/3.f, k1x * dtv, (2.f/9.f) * (k0x * dtv)));
        float cy = fmaf(4.f/9.f, k2y * dtv, fmaf(1.f/3.f, k1y * dtv, (2.f/9.f) * (k0y * dtv)));
        yv.x = fmaf(cx, dtv, yv.x);
        yv.y = fmaf(cy, dtv, yv.y);
        *(float2*)&S->y_lin[2 * tid] = yv;
    }
    __syncthreads();
    if (wid == 8) {
        float a = S->y_lin[lane] * S->lwv[lane];
        a = fmaf(S->y_lin[lane + 32], S->lwv[lane + 32], a);
        a = fmaf(S->y_lin[lane + 64], S->lwv[lane + 64], a);
        a = fmaf(S->y_lin[lane + 96], S->lwv[lane + 96], a);
        #pragma unroll
        for (int o = 16; o > 0; o >>= 1) a += __shfl_down_sync(0xffffffffu, a, o);
        if (lane == 0)
            out[(size_t)batch * NT + NT - 1] = 1.0f / (1.0f + expf(-(a + lbv)));
    }
    CLUSTER_SYNC();
}

extern "C" void kernel_launch(void* const* d_in, const int* in_sizes, int n_in,
                              void* d_out, int out_size) {
    const float* ts  = (const float*)d_in[0];
    const float* cd  = (const float*)d_in[1];
    const float* cc  = (const float*)d_in[2];
    const float* cb  = (const float*)d_in[3];
    const float* ca  = (const float*)d_in[4];
    const float* iW0 = (const float*)d_in[5];
    const float* ib0 = (const float*)d_in[6];
    const float* iW1 = (const float*)d_in[7];
    const float* ib1 = (const float*)d_in[8];
    const float* iW2 = (const float*)d_in[9];
    const float* ib2 = (const float*)d_in[10];
    const float* fW0 = (const float*)d_in[11];
    const float* fb0 = (const float*)d_in[12];
    const float* fW1 = (const float*)d_in[13];
    const float* fb1 = (const float*)d_in[14];
    const float* fW2 = (const float*)d_in[15];
    const float* fb2 = (const float*)d_in[16];
    const float* lW  = (const float*)d_in[17];
    const float* lb  = (const float*)d_in[18];
    float* o = (float*)d_out;

    prep_deriv<<<dim3(NB, NT / 16), 512>>>(ts, cd, cc, cb);
    cudaFuncSetAttribute(cde_kernel, cudaFuncAttributeMaxDynamicSharedMemorySize,
                         (int)sizeof(SM));
    cde_kernel<<<NB, NTHR, sizeof(SM)>>>(ts, ca,
                                         iW0, ib0, iW1, ib1, iW2, ib2,
                                         fW0, fb0, fW1, fb1, fW2, fb2,
                                         lW, lb, o);
}